// round 2
// baseline (speedup 1.0000x reference)
#include <cuda_runtime.h>

#define KS   13
#define RAD  6
#define TW   32
#define TH   8            // output rows per block (2 per thread, 4 warps)
#define PW   (TW + 2*RAD) // 44
#define PH   (TH + 2*RAD) // 20
#define IMH  256
#define IMW  256
#define NC   4
#define NB   2
#define NT   128

#define BIGNEG (-1.0e30f)

__device__ __forceinline__ float fast_ex2(float x) {
    float r; asm("ex2.approx.ftz.f32 %0, %1;" : "=f"(r) : "f"(x)); return r;
}
__device__ __forceinline__ float fast_lg2(float x) {
    float r; asm("lg2.approx.f32 %0, %1;" : "=f"(r) : "f"(x)); return r;
}
__device__ __forceinline__ float fast_exp(float x) {
    return fast_ex2(x * 1.4426950408889634f);
}

// ---- packed f32x2 ops (sm_103a) ------------------------------------------
__device__ __forceinline__ unsigned long long addx2(unsigned long long a, unsigned long long b) {
    unsigned long long r;
    asm("add.rn.f32x2 %0, %1, %2;" : "=l"(r) : "l"(a), "l"(b));
    return r;
}
__device__ __forceinline__ unsigned long long fmax2(unsigned long long a, unsigned long long b,
                                                    unsigned long long c) {
    unsigned long long r;
    asm("fma.rn.f32x2 %0, %1, %2, %3;" : "=l"(r) : "l"(a), "l"(b), "l"(c));
    return r;
}
__device__ __forceinline__ unsigned long long pack2(float lo, float hi) {
    unsigned long long r;
    asm("mov.b64 %0, {%1, %2};" : "=l"(r) : "f"(lo), "f"(hi));
    return r;
}
__device__ __forceinline__ void unpack2(unsigned long long v, float& lo, float& hi) {
    asm("mov.b64 {%0, %1}, %2;" : "=f"(lo), "=f"(hi) : "l"(v));
}

__global__ __launch_bounds__(NT, 6)
void bilateral13_v2(const float* __restrict__ x, float* __restrict__ out) {
    __shared__ float4 tile[PH][PW];
    __shared__ float  s_T[(KS + 2) * KS];   // 15 rows x 13; rows 0 and 14 = -inf sentinel

    const int tid = threadIdx.x;            // 0..127
    const int b   = blockIdx.z;
    const int tx0 = blockIdx.x * TW;
    const int ty0 = blockIdx.y * TH;

    // ---- log2-domain spatial table with sentinel rows ----------------------
    for (int e = tid; e < (KS + 2) * KS; e += NT) {
        const int k  = e / KS;              // table row 0..14
        const int ix = e % KS;
        float v = BIGNEG;
        if (k >= 1 && k <= KS) {
            const int iy = k - 1;
            float S = 0.f;
            #pragma unroll
            for (int i = 0; i < KS; i++) {
                float dd = (float)(i - RAD) * (1.0f / 3.0f);
                S += fast_exp(-0.5f * dd * dd);
            }
            float dy = (float)(iy - RAD) * (1.0f / 3.0f);
            float dx = (float)(ix - RAD) * (1.0f / 3.0f);
            v = fast_lg2((fast_exp(-0.5f * dy * dy) * fast_exp(-0.5f * dx * dx)) / (S * S));
        }
        s_T[e] = v;
    }

    // ---- cooperative load of reflect-padded tile, channels packed float4 --
    const float* xb = x + (size_t)b * NC * IMH * IMW;
    for (int i = tid; i < PH * PW; i += NT) {
        int py = i / PW, px = i % PW;
        int gy = ty0 + py - RAD;
        int gx = tx0 + px - RAD;
        gy = (gy < 0) ? -gy : ((gy >= IMH) ? (2 * IMH - 2 - gy) : gy);
        gx = (gx < 0) ? -gx : ((gx >= IMW) ? (2 * IMW - 2 - gx) : gx);
        int g = gy * IMW + gx;
        float4 v;
        v.x = xb[0 * IMH * IMW + g];
        v.y = xb[1 * IMH * IMW + g];
        v.z = xb[2 * IMH * IMW + g];
        v.w = xb[3 * IMH * IMW + g];
        tile[py][px] = v;
    }
    __syncthreads();

    // ---- each thread: two vertically adjacent output pixels ----------------
    const int lx  = tid & (TW - 1);  // 0..31
    const int lyw = tid >> 5;        // 0..3
    const int cy1 = 2 * lyw + RAD;   // tile row of center 1
    // center 2 = cy1 + 1

    const float4 c1 = tile[cy1][lx + RAD];
    const float4 c2 = tile[cy1 + 1][lx + RAD];

    const unsigned long long M = 0x7fffffff7fffffffULL;
    const unsigned long long nc01a = pack2(-c1.x, -c1.y);
    const unsigned long long nc23a = pack2(-c1.z, -c1.w);
    const unsigned long long nc01b = pack2(-c2.x, -c2.y);
    const unsigned long long nc23b = pack2(-c2.z, -c2.w);

    const float K2 = (-0.5f / 9.0f) * 1.4426950408889634f;  // log2-domain scale

    unsigned long long acc01a = 0, acc23a = 0, acc01b = 0, acc23b = 0;
    float ws1 = 0.f, ws2 = 0.f;

    #pragma unroll 1
    for (int j = 0; j < KS + 1; j++) {      // 14 absolute rows cover both windows
        const float4* rp    = &tile[2 * lyw + j][lx];
        const float*  Trow1 = &s_T[(j + 1) * KS];  // center1: spatial row j   (j<=12), else -inf
        const float*  Trow2 = &s_T[j * KS];        // center2: spatial row j-1 (j>=1),  else -inf
        #pragma unroll
        for (int ix = 0; ix < KS; ix++) {
            const ulonglong2 pv = *reinterpret_cast<const ulonglong2*>(&rp[ix]);
            const unsigned long long p01 = pv.x, p23 = pv.y;

            // --- center 1 ---
            {
                unsigned long long t01 = addx2(p01, nc01a);
                unsigned long long t23 = addx2(p23, nc23a);
                unsigned long long s   = addx2(t01 & M, t23 & M);
                float slo, shi; unpack2(s, slo, shi);
                float d = slo + shi;
                float w = fast_ex2(fmaf(d * d, K2, Trow1[ix]));
                ws1 += w;
                unsigned long long w2 = pack2(w, w);
                acc01a = fmax2(w2, p01, acc01a);
                acc23a = fmax2(w2, p23, acc23a);
            }
            // --- center 2 ---
            {
                unsigned long long t01 = addx2(p01, nc01b);
                unsigned long long t23 = addx2(p23, nc23b);
                unsigned long long s   = addx2(t01 & M, t23 & M);
                float slo, shi; unpack2(s, slo, shi);
                float d = slo + shi;
                float w = fast_ex2(fmaf(d * d, K2, Trow2[ix]));
                ws2 += w;
                unsigned long long w2 = pack2(w, w);
                acc01b = fmax2(w2, p01, acc01b);
                acc23b = fmax2(w2, p23, acc23b);
            }
        }
    }

    // ---- epilogue ----------------------------------------------------------
    float* ob = out + (size_t)b * NC * IMH * IMW;
    const float inv1 = __fdividef(1.0f, ws1);
    const float inv2 = __fdividef(1.0f, ws2);
    const int y1 = ty0 + 2 * lyw;
    const int o1 = y1 * IMW + tx0 + lx;
    const int o2 = o1 + IMW;

    float a0, a1, a2, a3;
    unpack2(acc01a, a0, a1); unpack2(acc23a, a2, a3);
    ob[0 * IMH * IMW + o1] = a0 * inv1;
    ob[1 * IMH * IMW + o1] = a1 * inv1;
    ob[2 * IMH * IMW + o1] = a2 * inv1;
    ob[3 * IMH * IMW + o1] = a3 * inv1;

    unpack2(acc01b, a0, a1); unpack2(acc23b, a2, a3);
    ob[0 * IMH * IMW + o2] = a0 * inv2;
    ob[1 * IMH * IMW + o2] = a1 * inv2;
    ob[2 * IMH * IMW + o2] = a2 * inv2;
    ob[3 * IMH * IMW + o2] = a3 * inv2;
}

extern "C" void kernel_launch(void* const* d_in, const int* in_sizes, int n_in,
                              void* d_out, int out_size) {
    const float* x = (const float*)d_in[0];
    float* out = (float*)d_out;
    dim3 grid(IMW / TW, IMH / TH, NB);   // 8 x 32 x 2 = 512 blocks
    bilateral13_v2<<<grid, NT>>>(x, out);
}

// round 3
// speedup vs baseline: 1.2003x; 1.2003x over previous
#include <cuda_runtime.h>

#define KS   13
#define RAD  6
#define TW   32
#define TH   4            // 32x4 outputs per block, 1 per thread
#define PW   (TW + 2*RAD) // 44
#define PH   (TH + 2*RAD) // 16
#define IMH  256
#define IMW  256
#define NC   4
#define NB   2
#define NT   128

__device__ __forceinline__ float fast_ex2(float x) {
    float r; asm("ex2.approx.ftz.f32 %0, %1;" : "=f"(r) : "f"(x)); return r;
}

__global__ __launch_bounds__(NT, 8)
void bilateral13_v3(const float* __restrict__ x, float* __restrict__ out) {
    __shared__ float4 tile[PH][PW];
    __shared__ float  s_T[KS * KS];   // K2 * ((iy-6)^2 + (ix-6)^2)

    const int tid = threadIdx.x;      // 0..127
    const int b   = blockIdx.z;
    const int tx0 = blockIdx.x * TW;
    const int ty0 = blockIdx.y * TH;

    // exponent scale shared by color and space terms:
    //   -0.5/sigma^2 * log2(e), sigma_color = sigma_space = 3
    const float K2 = (-0.5f / 9.0f) * 1.4426950408889634f;

    // ---- spatial table: pure arithmetic, normalization constant cancels ----
    for (int e = tid; e < KS * KS; e += NT) {
        const int iy = e / KS - RAD;
        const int ix = e % KS - RAD;
        s_T[e] = K2 * (float)(iy * iy + ix * ix);
    }

    // ---- cooperative load of reflect-padded tile, channels packed float4 --
    const float* xb = x + (size_t)b * NC * IMH * IMW;
    #pragma unroll
    for (int it = 0; it < (PH * PW + NT - 1) / NT; it++) {
        int i = tid + it * NT;
        if (i < PH * PW) {
            int py = i / PW, px = i % PW;
            int gy = ty0 + py - RAD;
            int gx = tx0 + px - RAD;
            gy = (gy < 0) ? -gy : ((gy >= IMH) ? (2 * IMH - 2 - gy) : gy);
            gx = (gx < 0) ? -gx : ((gx >= IMW) ? (2 * IMW - 2 - gx) : gx);
            int g = gy * IMW + gx;
            float4 v;
            v.x = xb[0 * IMH * IMW + g];
            v.y = xb[1 * IMH * IMW + g];
            v.z = xb[2 * IMH * IMW + g];
            v.w = xb[3 * IMH * IMW + g];
            tile[py][px] = v;
        }
    }
    __syncthreads();

    // ---- per-thread: one output pixel --------------------------------------
    const int lx = tid & (TW - 1);    // 0..31
    const int ly = tid >> 5;          // 0..3

    const float4 c = tile[ly + RAD][lx + RAD];

    float acc0 = 0.f, acc1 = 0.f, acc2 = 0.f, acc3 = 0.f, wsum = 0.f;

    #pragma unroll 1
    for (int iy = 0; iy < KS; iy++) {
        const float4* row  = &tile[ly + iy][lx];
        const float*  Trow = &s_T[iy * KS];
        #pragma unroll
        for (int ix = 0; ix < KS; ix++) {
            float4 p = row[ix];
            float d = fabsf(p.x - c.x) + fabsf(p.y - c.y)
                    + fabsf(p.z - c.z) + fabsf(p.w - c.w);
            float w = fast_ex2(fmaf(d * d, K2, Trow[ix]));
            wsum += w;
            acc0 = fmaf(w, p.x, acc0);
            acc1 = fmaf(w, p.y, acc1);
            acc2 = fmaf(w, p.z, acc2);
            acc3 = fmaf(w, p.w, acc3);
        }
    }

    const float inv = __fdividef(1.0f, wsum);
    float* ob = out + (size_t)b * NC * IMH * IMW;
    const int o = (ty0 + ly) * IMW + (tx0 + lx);
    ob[0 * IMH * IMW + o] = acc0 * inv;
    ob[1 * IMH * IMW + o] = acc1 * inv;
    ob[2 * IMH * IMW + o] = acc2 * inv;
    ob[3 * IMH * IMW + o] = acc3 * inv;
}

extern "C" void kernel_launch(void* const* d_in, const int* in_sizes, int n_in,
                              void* d_out, int out_size) {
    const float* x = (const float*)d_in[0];
    float* out = (float*)d_out;
    dim3 grid(IMW / TW, IMH / TH, NB);   // 8 x 64 x 2 = 1024 blocks
    bilateral13_v3<<<grid, NT>>>(x, out);
}

// round 4
// speedup vs baseline: 1.2166x; 1.0135x over previous
#include <cuda_runtime.h>

#define KS   13
#define RAD  6
#define TW   32
#define TH   4            // 32x4 outputs per block, 1 per thread
#define PW   (TW + 2*RAD) // 44
#define PH   (TH + 2*RAD) // 16
#define IMH  256
#define IMW  256
#define NC   4
#define NB   2
#define NT   128

__device__ __forceinline__ float fast_ex2(float x) {
    float r; asm("ex2.approx.ftz.f32 %0, %1;" : "=f"(r) : "f"(x)); return r;
}

__global__ __launch_bounds__(NT, 8)
void bilateral13_v4(const float* __restrict__ x, float* __restrict__ out) {
    __shared__ float4 tile[PH][PW];   // (u01, v01, u23, v23) basis
    __shared__ float  s_T[KS * KS];   // K2 * ((iy-6)^2 + (ix-6)^2)

    const int tid = threadIdx.x;      // 0..127
    const int b   = blockIdx.z;
    const int tx0 = blockIdx.x * TW;
    const int ty0 = blockIdx.y * TH;

    // shared exponent scale (sigma_color = sigma_space = 3):
    //   K2 = -0.5/9 * log2(e); normalization constant cancels in the ratio.
    const float K2 = (-0.5f / 9.0f) * 1.4426950408889634f;

    // ---- spatial table ----
    for (int e = tid; e < KS * KS; e += NT) {
        const int iy = e / KS - RAD;
        const int ix = e % KS - RAD;
        s_T[e] = K2 * (float)(iy * iy + ix * ix);
    }

    // ---- cooperative load of reflect-padded tile, (u,v) basis change ----
    const float* xb = x + (size_t)b * NC * IMH * IMW;
    #pragma unroll
    for (int it = 0; it < (PH * PW + NT - 1) / NT; it++) {
        int i = tid + it * NT;
        if (i < PH * PW) {
            int py = i / PW, px = i % PW;
            int gy = ty0 + py - RAD;
            int gx = tx0 + px - RAD;
            gy = (gy < 0) ? -gy : ((gy >= IMH) ? (2 * IMH - 2 - gy) : gy);
            gx = (gx < 0) ? -gx : ((gx >= IMW) ? (2 * IMW - 2 - gx) : gx);
            int g = gy * IMW + gx;
            float p0 = xb[0 * IMH * IMW + g];
            float p1 = xb[1 * IMH * IMW + g];
            float p2 = xb[2 * IMH * IMW + g];
            float p3 = xb[3 * IMH * IMW + g];
            float4 v;
            v.x = p0 + p1;   // u01
            v.y = p0 - p1;   // v01
            v.z = p2 + p3;   // u23
            v.w = p2 - p3;   // v23
            tile[py][px] = v;
        }
    }
    __syncthreads();

    // ---- per-thread: one output pixel ----
    const int lx = tid & (TW - 1);    // 0..31
    const int ly = tid >> 5;          // 0..3

    const float4 c = tile[ly + RAD][lx + RAD];

    float accU01 = 0.f, accV01 = 0.f, accU23 = 0.f, accV23 = 0.f, wsum = 0.f;

    #pragma unroll 1
    for (int iy = 0; iy < KS; iy++) {
        const float4* row  = &tile[ly + iy][lx];
        const float*  Trow = &s_T[iy * KS];
        #pragma unroll
        for (int ix = 0; ix < KS; ix++) {
            float4 p = row[ix];
            // |d0|+|d1| = max(|du01|, |dv01|); likewise channels 2,3.
            // FADD x2 + FMNMX (ALU, abs source mods) per pair.
            float m01 = fmaxf(fabsf(p.x - c.x), fabsf(p.y - c.y));
            float m23 = fmaxf(fabsf(p.z - c.z), fabsf(p.w - c.w));
            float d   = m01 + m23;
            float w = fast_ex2(fmaf(d * d, K2, Trow[ix]));
            wsum += w;
            accU01 = fmaf(w, p.x, accU01);
            accV01 = fmaf(w, p.y, accV01);
            accU23 = fmaf(w, p.z, accU23);
            accV23 = fmaf(w, p.w, accV23);
        }
    }

    // ---- epilogue: undo basis change, normalize ----
    const float hinv = 0.5f * __fdividef(1.0f, wsum);
    float* ob = out + (size_t)b * NC * IMH * IMW;
    const int o = (ty0 + ly) * IMW + (tx0 + lx);
    ob[0 * IMH * IMW + o] = (accU01 + accV01) * hinv;
    ob[1 * IMH * IMW + o] = (accU01 - accV01) * hinv;
    ob[2 * IMH * IMW + o] = (accU23 + accV23) * hinv;
    ob[3 * IMH * IMW + o] = (accU23 - accV23) * hinv;
}

extern "C" void kernel_launch(void* const* d_in, const int* in_sizes, int n_in,
                              void* d_out, int out_size) {
    const float* x = (const float*)d_in[0];
    float* out = (float*)d_out;
    dim3 grid(IMW / TW, IMH / TH, NB);   // 8 x 64 x 2 = 1024 blocks
    bilateral13_v4<<<grid, NT>>>(x, out);
}